// round 10
// baseline (speedup 1.0000x reference)
#include <cuda_runtime.h>
#include <cuda_bf16.h>
#include <cstdint>

// W8A8 GEMM via bf16 HMMA: out = alpha * (x @ w^T) + bias
// Round 10: 64x64 warp tiles (4 warps/CTA), fragment double-buffering.
// Pack: int32 -> bf16 (exact for |v|<=127). GEMM: mma.m16n8k16.bf16, 3-stage cp.async.

namespace {
constexpr int Mtot = 8192;
constexpr int Ntot = 4096;
constexpr int Ktot = 4096;
constexpr int BM = 128;
constexpr int BN = 128;
constexpr int BK = 64;        // bf16 elems per stage along K -> 128B rows (SW128)
constexpr int BKB = 128;      // row bytes in smem
constexpr int NS = 3;
constexpr int NTH = 128;      // 4 warps: 2 (M) x 2 (N); warp tile 64x64
constexpr int NKT = Ktot / BK;                 // 64
constexpr int STAGE_BYTES = (BM + BN) * BKB;   // 32 KB
constexpr int SMEM_TOTAL = NS * STAGE_BYTES;   // 96 KB

__device__ __forceinline__ uint32_t swz(int row, int kbyte) {
    return (uint32_t)(row * BKB + ((((kbyte >> 4) ^ (row & 7)) & 7) << 4) + (kbyte & 15));
}

__device__ __forceinline__ void cp_async16(uint32_t saddr, const void* gptr) {
    asm volatile("cp.async.cg.shared.global [%0], [%1], 16;\n" :: "r"(saddr), "l"(gptr));
}
__device__ __forceinline__ void cp_commit() {
    asm volatile("cp.async.commit_group;\n" ::);
}
template <int N>
__device__ __forceinline__ void cp_wait() {
    asm volatile("cp.async.wait_group %0;\n" :: "n"(N));
}

__device__ __forceinline__ void ldm4(uint32_t& r0, uint32_t& r1, uint32_t& r2, uint32_t& r3,
                                     uint32_t addr) {
    asm volatile("ldmatrix.sync.aligned.m8n8.x4.shared.b16 {%0,%1,%2,%3}, [%4];"
                 : "=r"(r0), "=r"(r1), "=r"(r2), "=r"(r3) : "r"(addr));
}

__device__ __forceinline__ void mma_bf16(float* d, const uint32_t* a, const uint32_t* b) {
    asm volatile("mma.sync.aligned.m16n8k16.row.col.f32.bf16.bf16.f32 "
                 "{%0,%1,%2,%3}, {%4,%5,%6,%7}, {%8,%9}, {%0,%1,%2,%3};"
                 : "+f"(d[0]), "+f"(d[1]), "+f"(d[2]), "+f"(d[3])
                 : "r"(a[0]), "r"(a[1]), "r"(a[2]), "r"(a[3]), "r"(b[0]), "r"(b[1]));
}

__device__ __forceinline__ uint32_t bf16_of_int(int v) {
    return __float_as_uint((float)v) >> 16;
}
__device__ __forceinline__ uint32_t pack2bf(int lo, int hi) {
    return bf16_of_int(lo) | (bf16_of_int(hi) << 16);
}
}  // namespace

// bf16 scratch (device globals: sanctioned no-alloc scratch). 64 MB + 32 MB.
__device__ __align__(16) uint16_t g_xh[(size_t)Mtot * Ktot];
__device__ __align__(16) uint16_t g_wh[(size_t)Ntot * Ktot];

// -------- Stage 1: merged int32 -> bf16 pack (8 elems / thread) --------
__global__ void pack_kernel(const int* __restrict__ xsrc, const int* __restrict__ wsrc) {
    constexpr int nx8 = Mtot * Ktot / 8;
    constexpr int nw8 = Ntot * Ktot / 8;
    const int i = blockIdx.x * blockDim.x + threadIdx.x;
    const int* src;
    uint16_t* dst;
    int j;
    if (i < nx8) {
        src = xsrc; dst = g_xh; j = i;
    } else if (i < nx8 + nw8) {
        src = wsrc; dst = g_wh; j = i - nx8;
    } else {
        return;
    }
    const int4* s = reinterpret_cast<const int4*>(src) + (size_t)j * 2;
    int4 a = s[0], b = s[1];
    uint4 o;
    o.x = pack2bf(a.x, a.y);
    o.y = pack2bf(a.z, a.w);
    o.z = pack2bf(b.x, b.y);
    o.w = pack2bf(b.z, b.w);
    reinterpret_cast<uint4*>(dst)[j] = o;
}

namespace {
// Load one 32KB stage with 128 threads: thread t owns A row t and B row t
// (8 x 16B chunks each -> 16 cp.async / thread).
__device__ __forceinline__ void load_stage(uint32_t sA, uint32_t sB,
                                           const uint16_t* X, const uint16_t* W,
                                           int bm, int bn, int kbase, int tid) {
    const int row = tid;
    const uint16_t* xg = X + (size_t)(bm + row) * Ktot + kbase;
    const uint16_t* wg = W + (size_t)(bn + row) * Ktot + kbase;
    const uint32_t rbase = (uint32_t)(row * BKB);
    const int rx = row & 7;
#pragma unroll
    for (int c = 0; c < 8; c++) {
        const uint32_t sw = rbase + (uint32_t)(((c ^ rx) & 7) << 4);
        cp_async16(sA + sw, xg + c * 8);
        cp_async16(sB + sw, wg + c * 8);
    }
}
}  // namespace

// -------- Stage 2: bf16 HMMA GEMM, 64x64 warp tiles --------
__global__ void __launch_bounds__(NTH, 2)
w8a8_gemm_kernel(const float* __restrict__ bias, const float* __restrict__ alphap,
                 float* __restrict__ out) {
    extern __shared__ __align__(128) int8_t smem[];
    const uint32_t sbase = (uint32_t)__cvta_generic_to_shared(smem);

    const uint16_t* __restrict__ X = g_xh;
    const uint16_t* __restrict__ W = g_wh;

    const int tid = threadIdx.x;
    const int lane = tid & 31;
    const int warp = tid >> 5;
    const int wm = warp >> 1;  // 0..1 -> 64 rows each
    const int wn = warp & 1;   // 0..1 -> 64 cols each

    const int bm = blockIdx.y * BM;
    const int bn = blockIdx.x * BN;

    // ldmatrix per-lane address components (fragment order verified earlier rounds).
    const int l8 = lane & 7;
    const int g4 = lane >> 3;
    const int aRowOff = ((g4 & 1) << 3) + l8;   // A x4: m16 x k16
    const int aKoff = (g4 >> 1) << 4;           // bytes
    const int bRowOff = ((g4 >> 1) << 3) + l8;  // B x4: two n8 x k16
    const int bKoff = (g4 & 1) << 4;            // bytes

    float acc[4][8][4];
#pragma unroll
    for (int mt = 0; mt < 4; mt++)
#pragma unroll
        for (int nt = 0; nt < 8; nt++)
#pragma unroll
            for (int i = 0; i < 4; i++) acc[mt][nt][i] = 0.0f;

    // ---- prologue: stages 0..NS-2 ----
#pragma unroll
    for (int st = 0; st < NS - 1; st++) {
        const uint32_t sA = sbase + st * STAGE_BYTES;
        load_stage(sA, sA + BM * BKB, X, W, bm, bn, st * BK, tid);
        cp_commit();
    }

    uint32_t af[2][4][4];  // double-buffered A fragments (4 m16 tiles)
    uint32_t bf[2][8][2];  // double-buffered B fragments (8 n8 tiles)

    int slot = 0;
    for (int kt = 0; kt < NKT; kt++) {
        cp_wait<NS - 2>();
        __syncthreads();

        // Prefetch stage kt+NS-1 before compute -> 2 iters of latency slack.
        const int pf = kt + NS - 1;
        if (pf < NKT) {
            const int ps = (slot + NS - 1 >= NS) ? slot - 1 : slot + NS - 1;
            const uint32_t sA = sbase + ps * STAGE_BYTES;
            load_stage(sA, sA + BM * BKB, X, W, bm, bn, pf * BK, tid);
        }
        cp_commit();

        const uint32_t sAc = sbase + slot * STAGE_BYTES;
        const uint32_t sBc = sAc + BM * BKB;

        // Load fragments for ks=0 into buffer 0.
#pragma unroll
        for (int mt = 0; mt < 4; mt++) {
            const int row = wm * 64 + mt * 16 + aRowOff;
            ldm4(af[0][mt][0], af[0][mt][1], af[0][mt][2], af[0][mt][3],
                 sAc + swz(row, aKoff));
        }
#pragma unroll
        for (int p = 0; p < 4; p++) {
            const int row = wn * 64 + p * 16 + bRowOff;
            uint32_t r0, r1, r2, r3;
            ldm4(r0, r1, r2, r3, sBc + swz(row, bKoff));
            bf[0][2 * p][0] = r0;
            bf[0][2 * p][1] = r1;
            bf[0][2 * p + 1][0] = r2;
            bf[0][2 * p + 1][1] = r3;
        }

#pragma unroll
        for (int ks = 0; ks < 4; ks++) {
            const int cur = ks & 1;
            if (ks < 3) {  // prefetch fragments for ks+1 into alternate buffer
                const int nxt = cur ^ 1;
                const int kb = (ks + 1) * 32;
#pragma unroll
                for (int mt = 0; mt < 4; mt++) {
                    const int row = wm * 64 + mt * 16 + aRowOff;
                    ldm4(af[nxt][mt][0], af[nxt][mt][1], af[nxt][mt][2], af[nxt][mt][3],
                         sAc + swz(row, kb + aKoff));
                }
#pragma unroll
                for (int p = 0; p < 4; p++) {
                    const int row = wn * 64 + p * 16 + bRowOff;
                    uint32_t r0, r1, r2, r3;
                    ldm4(r0, r1, r2, r3, sBc + swz(row, kb + bKoff));
                    bf[nxt][2 * p][0] = r0;
                    bf[nxt][2 * p][1] = r1;
                    bf[nxt][2 * p + 1][0] = r2;
                    bf[nxt][2 * p + 1][1] = r3;
                }
            }
#pragma unroll
            for (int mt = 0; mt < 4; mt++)
#pragma unroll
                for (int nt = 0; nt < 8; nt++)
                    mma_bf16(acc[mt][nt], af[cur][mt], bf[cur][nt]);
        }

        slot = (slot + 1 == NS) ? 0 : slot + 1;
    }

    // ---- epilogue: out = alpha*acc + bias ----
    const float alpha = alphap[0];
    const int g = lane >> 2;
    const int tig = lane & 3;

#pragma unroll
    for (int nt = 0; nt < 8; nt++) {
        const int col = bn + wn * 64 + nt * 8 + tig * 2;
        const float b0 = bias[col];
        const float b1 = bias[col + 1];
#pragma unroll
        for (int mt = 0; mt < 4; mt++) {
            const int row0 = bm + wm * 64 + mt * 16 + g;
            float2 v0, v1;
            v0.x = fmaf(alpha, acc[mt][nt][0], b0);
            v0.y = fmaf(alpha, acc[mt][nt][1], b1);
            v1.x = fmaf(alpha, acc[mt][nt][2], b0);
            v1.y = fmaf(alpha, acc[mt][nt][3], b1);
            *reinterpret_cast<float2*>(out + (size_t)row0 * Ntot + col) = v0;
            *reinterpret_cast<float2*>(out + (size_t)(row0 + 8) * Ntot + col) = v1;
        }
    }
}

extern "C" void kernel_launch(void* const* d_in, const int* in_sizes, int n_in,
                              void* d_out, int out_size) {
    const int* X32 = (const int*)d_in[0];
    const int* W32 = (const int*)d_in[1];
    const float* bias = (const float*)d_in[2];
    const float* alpha = (const float*)d_in[3];
    float* out = (float*)d_out;

    const int n8 = (Mtot * Ktot + Ntot * Ktot) / 8;
    pack_kernel<<<(n8 + 255) / 256, 256>>>(X32, W32);

    static bool attr_set = false;
    if (!attr_set) {
        cudaFuncSetAttribute(w8a8_gemm_kernel,
                             cudaFuncAttributeMaxDynamicSharedMemorySize, SMEM_TOTAL);
        attr_set = true;
    }
    dim3 grid(Ntot / BN, Mtot / BM);  // (32, 64)
    w8a8_gemm_kernel<<<grid, NTH, SMEM_TOTAL>>>(bias, alpha, out);
}

// round 11
// speedup vs baseline: 1.3741x; 1.3741x over previous
#include <cuda_runtime.h>
#include <cuda_bf16.h>
#include <cstdint>

// W8A8 GEMM via bf16 HMMA: out = alpha * (x @ w^T) + bias
// Round 11: CTA 128x64, warp tile 32x32, NS=3 (72KB smem) -> 3 CTAs/SM, 24 warps/SM.
// Pack: int32 -> bf16 (exact for |v|<=127). GEMM: mma.m16n8k16.bf16, cp.async ring.

namespace {
constexpr int Mtot = 8192;
constexpr int Ntot = 4096;
constexpr int Ktot = 4096;
constexpr int BM = 128;
constexpr int BN = 64;
constexpr int BK = 64;        // bf16 elems per stage along K -> 128B rows (SW128)
constexpr int BKB = 128;      // row bytes in smem
constexpr int NS = 3;
constexpr int NTH = 256;      // 8 warps: 4 (M) x 2 (N); warp tile 32x32
constexpr int NKT = Ktot / BK;                 // 64
constexpr int STAGE_BYTES = (BM + BN) * BKB;   // 24 KB
constexpr int SMEM_TOTAL = NS * STAGE_BYTES;   // 72 KB

__device__ __forceinline__ uint32_t swz(int row, int kbyte) {
    return (uint32_t)(row * BKB + ((((kbyte >> 4) ^ (row & 7)) & 7) << 4) + (kbyte & 15));
}

__device__ __forceinline__ void cp_async16(uint32_t saddr, const void* gptr) {
    asm volatile("cp.async.cg.shared.global [%0], [%1], 16;\n" :: "r"(saddr), "l"(gptr));
}
__device__ __forceinline__ void cp_commit() {
    asm volatile("cp.async.commit_group;\n" ::);
}
template <int N>
__device__ __forceinline__ void cp_wait() {
    asm volatile("cp.async.wait_group %0;\n" :: "n"(N));
}

__device__ __forceinline__ void ldm4(uint32_t& r0, uint32_t& r1, uint32_t& r2, uint32_t& r3,
                                     uint32_t addr) {
    asm volatile("ldmatrix.sync.aligned.m8n8.x4.shared.b16 {%0,%1,%2,%3}, [%4];"
                 : "=r"(r0), "=r"(r1), "=r"(r2), "=r"(r3) : "r"(addr));
}

__device__ __forceinline__ void mma_bf16(float* d, const uint32_t* a, const uint32_t* b) {
    asm volatile("mma.sync.aligned.m16n8k16.row.col.f32.bf16.bf16.f32 "
                 "{%0,%1,%2,%3}, {%4,%5,%6,%7}, {%8,%9}, {%0,%1,%2,%3};"
                 : "+f"(d[0]), "+f"(d[1]), "+f"(d[2]), "+f"(d[3])
                 : "r"(a[0]), "r"(a[1]), "r"(a[2]), "r"(a[3]), "r"(b[0]), "r"(b[1]));
}

__device__ __forceinline__ uint32_t bf16_of_int(int v) {
    return __float_as_uint((float)v) >> 16;
}
__device__ __forceinline__ uint32_t pack2bf(int lo, int hi) {
    return bf16_of_int(lo) | (bf16_of_int(hi) << 16);
}
}  // namespace

// bf16 scratch (device globals: sanctioned no-alloc scratch). 64 MB + 32 MB.
__device__ __align__(16) uint16_t g_xh[(size_t)Mtot * Ktot];
__device__ __align__(16) uint16_t g_wh[(size_t)Ntot * Ktot];

// -------- Stage 1: merged int32 -> bf16 pack (8 elems / thread) --------
__global__ void pack_kernel(const int* __restrict__ xsrc, const int* __restrict__ wsrc) {
    constexpr int nx8 = Mtot * Ktot / 8;
    constexpr int nw8 = Ntot * Ktot / 8;
    const int i = blockIdx.x * blockDim.x + threadIdx.x;
    const int* src;
    uint16_t* dst;
    int j;
    if (i < nx8) {
        src = xsrc; dst = g_xh; j = i;
    } else if (i < nx8 + nw8) {
        src = wsrc; dst = g_wh; j = i - nx8;
    } else {
        return;
    }
    const int4* s = reinterpret_cast<const int4*>(src) + (size_t)j * 2;
    int4 a = s[0], b = s[1];
    uint4 o;
    o.x = pack2bf(a.x, a.y);
    o.y = pack2bf(a.z, a.w);
    o.z = pack2bf(b.x, b.y);
    o.w = pack2bf(b.z, b.w);
    reinterpret_cast<uint4*>(dst)[j] = o;
}

namespace {
// Load one 24KB stage with 256 threads:
// A: 128 rows x 8 chunks -> thread t: row t>>1, chunks (t&1)*4..+3   (1024 chunks)
// B:  64 rows x 8 chunks -> thread t: row t>>2, chunks (t&3)*2..+1   ( 512 chunks)
__device__ __forceinline__ void load_stage(uint32_t sA, uint32_t sB,
                                           const uint16_t* X, const uint16_t* W,
                                           int bm, int bn, int kbase, int tid) {
    {
        const int row = tid >> 1;
        const int c0 = (tid & 1) * 4;
        const uint16_t* xg = X + (size_t)(bm + row) * Ktot + kbase + c0 * 8;
        const uint32_t rbase = (uint32_t)(row * BKB);
        const int rx = row & 7;
#pragma unroll
        for (int c = 0; c < 4; c++) {
            const uint32_t sw = rbase + (uint32_t)((((c0 + c) ^ rx) & 7) << 4);
            cp_async16(sA + sw, xg + c * 8);
        }
    }
    {
        const int row = tid >> 2;
        const int c0 = (tid & 3) * 2;
        const uint16_t* wg = W + (size_t)(bn + row) * Ktot + kbase + c0 * 8;
        const uint32_t rbase = (uint32_t)(row * BKB);
        const int rx = row & 7;
#pragma unroll
        for (int c = 0; c < 2; c++) {
            const uint32_t sw = rbase + (uint32_t)((((c0 + c) ^ rx) & 7) << 4);
            cp_async16(sB + sw, wg + c * 8);
        }
    }
}
}  // namespace

// -------- Stage 2: bf16 HMMA GEMM, 32x32 warp tiles, 3 CTAs/SM --------
__global__ void __launch_bounds__(NTH, 3)
w8a8_gemm_kernel(const float* __restrict__ bias, const float* __restrict__ alphap,
                 float* __restrict__ out) {
    extern __shared__ __align__(128) int8_t smem[];
    const uint32_t sbase = (uint32_t)__cvta_generic_to_shared(smem);

    const uint16_t* __restrict__ X = g_xh;
    const uint16_t* __restrict__ W = g_wh;

    const int tid = threadIdx.x;
    const int lane = tid & 31;
    const int warp = tid >> 5;
    const int wm = warp >> 1;  // 0..3 -> 32 rows each
    const int wn = warp & 1;   // 0..1 -> 32 cols each

    const int bm = blockIdx.y * BM;
    const int bn = blockIdx.x * BN;

    // ldmatrix per-lane address components (fragment order verified earlier rounds).
    const int l8 = lane & 7;
    const int g4 = lane >> 3;
    const int aRowOff = ((g4 & 1) << 3) + l8;   // A x4: m16 x k16
    const int aKoff = (g4 >> 1) << 4;           // bytes
    const int bRowOff = ((g4 >> 1) << 3) + l8;  // B x4: two n8 x k16
    const int bKoff = (g4 & 1) << 4;            // bytes

    float acc[2][4][4];
#pragma unroll
    for (int mt = 0; mt < 2; mt++)
#pragma unroll
        for (int nt = 0; nt < 4; nt++)
#pragma unroll
            for (int i = 0; i < 4; i++) acc[mt][nt][i] = 0.0f;

    // ---- prologue: stages 0..NS-2 ----
#pragma unroll
    for (int st = 0; st < NS - 1; st++) {
        const uint32_t sA = sbase + st * STAGE_BYTES;
        load_stage(sA, sA + BM * BKB, X, W, bm, bn, st * BK, tid);
        cp_commit();
    }

    int slot = 0;
    for (int kt = 0; kt < NKT; kt++) {
        cp_wait<NS - 2>();
        __syncthreads();

        // Prefetch stage kt+NS-1 before compute -> 2 iters of latency slack.
        const int pf = kt + NS - 1;
        if (pf < NKT) {
            const int ps = (slot + NS - 1 >= NS) ? slot - 1 : slot + NS - 1;
            const uint32_t sA = sbase + ps * STAGE_BYTES;
            load_stage(sA, sA + BM * BKB, X, W, bm, bn, pf * BK, tid);
        }
        cp_commit();

        const uint32_t sAc = sbase + slot * STAGE_BYTES;
        const uint32_t sBc = sAc + BM * BKB;

#pragma unroll
        for (int ks = 0; ks < 4; ks++) {  // four k16 chunks per stage
            uint32_t a[2][4];
#pragma unroll
            for (int mt = 0; mt < 2; mt++) {
                const int row = wm * 32 + mt * 16 + aRowOff;
                ldm4(a[mt][0], a[mt][1], a[mt][2], a[mt][3],
                     sAc + swz(row, ks * 32 + aKoff));
            }
            uint32_t b[4][2];
#pragma unroll
            for (int p = 0; p < 2; p++) {
                const int row = wn * 32 + p * 16 + bRowOff;
                uint32_t r0, r1, r2, r3;
                ldm4(r0, r1, r2, r3, sBc + swz(row, ks * 32 + bKoff));
                b[2 * p][0] = r0;
                b[2 * p][1] = r1;
                b[2 * p + 1][0] = r2;
                b[2 * p + 1][1] = r3;
            }
#pragma unroll
            for (int mt = 0; mt < 2; mt++)
#pragma unroll
                for (int nt = 0; nt < 4; nt++)
                    mma_bf16(acc[mt][nt], a[mt], b[nt]);
        }

        slot = (slot + 1 == NS) ? 0 : slot + 1;
    }

    // ---- epilogue: out = alpha*acc + bias ----
    const float alpha = alphap[0];
    const int g = lane >> 2;
    const int tig = lane & 3;

#pragma unroll
    for (int nt = 0; nt < 4; nt++) {
        const int col = bn + wn * 32 + nt * 8 + tig * 2;
        const float b0 = bias[col];
        const float b1 = bias[col + 1];
#pragma unroll
        for (int mt = 0; mt < 2; mt++) {
            const int row0 = bm + wm * 32 + mt * 16 + g;
            float2 v0, v1;
            v0.x = fmaf(alpha, acc[mt][nt][0], b0);
            v0.y = fmaf(alpha, acc[mt][nt][1], b1);
            v1.x = fmaf(alpha, acc[mt][nt][2], b0);
            v1.y = fmaf(alpha, acc[mt][nt][3], b1);
            *reinterpret_cast<float2*>(out + (size_t)row0 * Ntot + col) = v0;
            *reinterpret_cast<float2*>(out + (size_t)(row0 + 8) * Ntot + col) = v1;
        }
    }
}

extern "C" void kernel_launch(void* const* d_in, const int* in_sizes, int n_in,
                              void* d_out, int out_size) {
    const int* X32 = (const int*)d_in[0];
    const int* W32 = (const int*)d_in[1];
    const float* bias = (const float*)d_in[2];
    const float* alpha = (const float*)d_in[3];
    float* out = (float*)d_out;

    const int n8 = (Mtot * Ktot + Ntot * Ktot) / 8;
    pack_kernel<<<(n8 + 255) / 256, 256>>>(X32, W32);

    static bool attr_set = false;
    if (!attr_set) {
        cudaFuncSetAttribute(w8a8_gemm_kernel,
                             cudaFuncAttributeMaxDynamicSharedMemorySize, SMEM_TOTAL);
        attr_set = true;
    }
    dim3 grid(Ntot / BN, Mtot / BM);  // (64, 64)
    w8a8_gemm_kernel<<<grid, NTH, SMEM_TOTAL>>>(bias, alpha, out);
}

// round 12
// speedup vs baseline: 1.9526x; 1.4210x over previous
#include <cuda_runtime.h>
#include <cuda_bf16.h>
#include <cstdint>

// W8A8 GEMM via bf16 HMMA: out = alpha * (x @ w^T) + bias
// Round 12 = Round 9 (best: 846us GEMM) with the prefetch cp.asyncs interleaved
// into the ks loop so the post-barrier critical path starts with LDSM, not an
// 8-deep cp.async issue burst (volatile asm order is frozen; placement = schedule).

namespace {
constexpr int Mtot = 8192;
constexpr int Ntot = 4096;
constexpr int Ktot = 4096;
constexpr int BM = 128;
constexpr int BN = 128;
constexpr int BK = 64;        // bf16 elems per stage along K -> 128B rows (SW128)
constexpr int BKB = 128;      // row bytes in smem
constexpr int NS = 3;
constexpr int NTH = 256;      // 8 warps: 4 (M) x 2 (N); warp tile 32x64
constexpr int NKT = Ktot / BK;                 // 64
constexpr int STAGE_BYTES = (BM + BN) * BKB;   // 32 KB
constexpr int SMEM_TOTAL = NS * STAGE_BYTES;   // 96 KB

__device__ __forceinline__ uint32_t swz(int row, int kbyte) {
    return (uint32_t)(row * BKB + ((((kbyte >> 4) ^ (row & 7)) & 7) << 4) + (kbyte & 15));
}

__device__ __forceinline__ void cp_async16(uint32_t saddr, const void* gptr) {
    asm volatile("cp.async.cg.shared.global [%0], [%1], 16;\n" :: "r"(saddr), "l"(gptr));
}
__device__ __forceinline__ void cp_commit() {
    asm volatile("cp.async.commit_group;\n" ::);
}
template <int N>
__device__ __forceinline__ void cp_wait() {
    asm volatile("cp.async.wait_group %0;\n" :: "n"(N));
}

__device__ __forceinline__ void ldm4(uint32_t& r0, uint32_t& r1, uint32_t& r2, uint32_t& r3,
                                     uint32_t addr) {
    asm volatile("ldmatrix.sync.aligned.m8n8.x4.shared.b16 {%0,%1,%2,%3}, [%4];"
                 : "=r"(r0), "=r"(r1), "=r"(r2), "=r"(r3) : "r"(addr));
}

__device__ __forceinline__ void mma_bf16(float* d, const uint32_t* a, const uint32_t* b) {
    asm volatile("mma.sync.aligned.m16n8k16.row.col.f32.bf16.bf16.f32 "
                 "{%0,%1,%2,%3}, {%4,%5,%6,%7}, {%8,%9}, {%0,%1,%2,%3};"
                 : "+f"(d[0]), "+f"(d[1]), "+f"(d[2]), "+f"(d[3])
                 : "r"(a[0]), "r"(a[1]), "r"(a[2]), "r"(a[3]), "r"(b[0]), "r"(b[1]));
}

__device__ __forceinline__ uint32_t bf16_of_int(int v) {
    return __float_as_uint((float)v) >> 16;
}
__device__ __forceinline__ uint32_t pack2bf(int lo, int hi) {
    return bf16_of_int(lo) | (bf16_of_int(hi) << 16);
}
}  // namespace

// bf16 scratch (device globals: sanctioned no-alloc scratch). 64 MB + 32 MB.
__device__ __align__(16) uint16_t g_xh[(size_t)Mtot * Ktot];
__device__ __align__(16) uint16_t g_wh[(size_t)Ntot * Ktot];

// -------- Stage 1: merged int32 -> bf16 pack (8 elems / thread) --------
__global__ void pack_kernel(const int* __restrict__ xsrc, const int* __restrict__ wsrc) {
    constexpr int nx8 = Mtot * Ktot / 8;
    constexpr int nw8 = Ntot * Ktot / 8;
    const int i = blockIdx.x * blockDim.x + threadIdx.x;
    const int* src;
    uint16_t* dst;
    int j;
    if (i < nx8) {
        src = xsrc; dst = g_xh; j = i;
    } else if (i < nx8 + nw8) {
        src = wsrc; dst = g_wh; j = i - nx8;
    } else {
        return;
    }
    const int4* s = reinterpret_cast<const int4*>(src) + (size_t)j * 2;
    int4 a = s[0], b = s[1];
    uint4 o;
    o.x = pack2bf(a.x, a.y);
    o.y = pack2bf(a.z, a.w);
    o.z = pack2bf(b.x, b.y);
    o.w = pack2bf(b.z, b.w);
    reinterpret_cast<uint4*>(dst)[j] = o;
}

// -------- Stage 2: bf16 HMMA GEMM, interleaved prefetch --------
__global__ void __launch_bounds__(NTH, 2)
w8a8_gemm_kernel(const float* __restrict__ bias, const float* __restrict__ alphap,
                 float* __restrict__ out) {
    extern __shared__ __align__(128) int8_t smem[];
    const uint32_t sbase = (uint32_t)__cvta_generic_to_shared(smem);

    const uint16_t* __restrict__ X = g_xh;
    const uint16_t* __restrict__ W = g_wh;

    const int tid = threadIdx.x;
    const int lane = tid & 31;
    const int warp = tid >> 5;
    const int wm = warp >> 1;  // 0..3 -> 32 rows each
    const int wn = warp & 1;   // 0..1 -> 64 cols each

    const int bm = blockIdx.y * BM;
    const int bn = blockIdx.x * BN;

    // ---- load mapping: thread t -> A row t>>1 and B row t>>1, chunks (t&1)*4..+3
    const int ldrow = tid >> 1;
    const int c0 = (tid & 1) * 4;
    const int rx = ldrow & 7;
    const uint32_t sArow = (uint32_t)(ldrow * BKB);
    // swizzled chunk offsets for the 4 chunks this thread writes
    uint32_t swoff[4];
#pragma unroll
    for (int c = 0; c < 4; c++)
        swoff[c] = sArow + (uint32_t)((((c0 + c) ^ rx) & 7) << 4);
    const uint16_t* Xrow = X + (size_t)(bm + ldrow) * Ktot + c0 * 8;
    const uint16_t* Wrow = W + (size_t)(bn + ldrow) * Ktot + c0 * 8;

    // ldmatrix per-lane address components.
    const int l8 = lane & 7;
    const int g4 = lane >> 3;
    const int aRowOff = ((g4 & 1) << 3) + l8;
    const int aKoff = (g4 >> 1) << 4;
    const int bRowOff = ((g4 >> 1) << 3) + l8;
    const int bKoff = (g4 & 1) << 4;

    float acc[2][8][4];
#pragma unroll
    for (int mt = 0; mt < 2; mt++)
#pragma unroll
        for (int nt = 0; nt < 8; nt++)
#pragma unroll
            for (int i = 0; i < 4; i++) acc[mt][nt][i] = 0.0f;

    // ---- prologue: stages 0..NS-2 ----
#pragma unroll
    for (int st = 0; st < NS - 1; st++) {
        const uint32_t sA = sbase + st * STAGE_BYTES;
        const uint32_t sB = sA + BM * BKB;
        const uint16_t* xg = Xrow + st * BK;
        const uint16_t* wg = Wrow + st * BK;
#pragma unroll
        for (int c = 0; c < 4; c++) {
            cp_async16(sA + swoff[c], xg + c * 8);
            cp_async16(sB + swoff[c], wg + c * 8);
        }
        cp_commit();
    }

    int slot = 0;
    for (int kt = 0; kt < NKT; kt++) {
        cp_wait<NS - 2>();
        __syncthreads();

        const int pf = kt + NS - 1;
        const bool do_pf = (pf < NKT);
        const int ps = (slot + NS - 1 >= NS) ? slot - 1 : slot + NS - 1;
        const uint32_t pA = sbase + ps * STAGE_BYTES;
        const uint32_t pB = pA + BM * BKB;
        const uint16_t* xg = Xrow + pf * BK;
        const uint16_t* wg = Wrow + pf * BK;

        const uint32_t sAc = sbase + slot * STAGE_BYTES;
        const uint32_t sBc = sAc + BM * BKB;

#pragma unroll
        for (int ks = 0; ks < 4; ks++) {  // four k16 chunks per stage
            // Fragment loads first: post-barrier critical path starts with LDSM.
            uint32_t a[2][4];
#pragma unroll
            for (int mt = 0; mt < 2; mt++) {
                const int row = wm * 32 + mt * 16 + aRowOff;
                ldm4(a[mt][0], a[mt][1], a[mt][2], a[mt][3],
                     sAc + swz(row, ks * 32 + aKoff));
            }
            uint32_t b[8][2];
#pragma unroll
            for (int p = 0; p < 4; p++) {
                const int row = wn * 64 + p * 16 + bRowOff;
                uint32_t r0, r1, r2, r3;
                ldm4(r0, r1, r2, r3, sBc + swz(row, ks * 32 + bKoff));
                b[2 * p][0] = r0;
                b[2 * p][1] = r1;
                b[2 * p + 1][0] = r2;
                b[2 * p + 1][1] = r3;
            }
            // Sprinkle 2 of this thread's 8 prefetch cp.asyncs per ks chunk;
            // they issue while HMMAs from prior chunks keep the tensor pipe fed.
            if (do_pf) {
                cp_async16(pA + swoff[ks], xg + ks * 8);
                cp_async16(pB + swoff[ks], wg + ks * 8);
            }
#pragma unroll
            for (int mt = 0; mt < 2; mt++)
#pragma unroll
                for (int nt = 0; nt < 8; nt++)
                    mma_bf16(acc[mt][nt], a[mt], b[nt]);
        }

        cp_commit();
        slot = (slot + 1 == NS) ? 0 : slot + 1;
    }

    // ---- epilogue: out = alpha*acc + bias ----
    const float alpha = alphap[0];
    const int g = lane >> 2;
    const int tig = lane & 3;

#pragma unroll
    for (int nt = 0; nt < 8; nt++) {
        const int col = bn + wn * 64 + nt * 8 + tig * 2;
        const float b0 = bias[col];
        const float b1 = bias[col + 1];
#pragma unroll
        for (int mt = 0; mt < 2; mt++) {
            const int row0 = bm + wm * 32 + mt * 16 + g;
            float2 v0, v1;
            v0.x = fmaf(alpha, acc[mt][nt][0], b0);
            v0.y = fmaf(alpha, acc[mt][nt][1], b1);
            v1.x = fmaf(alpha, acc[mt][nt][2], b0);
            v1.y = fmaf(alpha, acc[mt][nt][3], b1);
            *reinterpret_cast<float2*>(out + (size_t)row0 * Ntot + col) = v0;
            *reinterpret_cast<float2*>(out + (size_t)(row0 + 8) * Ntot + col) = v1;
        }
    }
}

extern "C" void kernel_launch(void* const* d_in, const int* in_sizes, int n_in,
                              void* d_out, int out_size) {
    const int* X32 = (const int*)d_in[0];
    const int* W32 = (const int*)d_in[1];
    const float* bias = (const float*)d_in[2];
    const float* alpha = (const float*)d_in[3];
    float* out = (float*)d_out;

    const int n8 = (Mtot * Ktot + Ntot * Ktot) / 8;
    pack_kernel<<<(n8 + 255) / 256, 256>>>(X32, W32);

    static bool attr_set = false;
    if (!attr_set) {
        cudaFuncSetAttribute(w8a8_gemm_kernel,
                             cudaFuncAttributeMaxDynamicSharedMemorySize, SMEM_TOTAL);
        attr_set = true;
    }
    dim3 grid(Ntot / BN, Mtot / BM);  // (32, 64)
    w8a8_gemm_kernel<<<grid, NTH, SMEM_TOTAL>>>(bias, alpha, out);
}